// round 13
// baseline (speedup 1.0000x reference)
#include <cuda_runtime.h>
#include <cuda_bf16.h>
#include <cstdint>

#define NPIX   32768      // 8*64*64 pixels
#define DDIM   512
#define NKEYS  2000
#define MKEYS  2048       // padded key count

// ---------------- scratch (static device arrays; allocation-free) ----------
__device__ __align__(256) __nv_bfloat16 g_qb[(size_t)NPIX * DDIM];   // 32 MB normalized q, bf16
__device__ __align__(256) float         g_qf[(size_t)NPIX * DDIM];   // 64 MB normalized q, fp32
__device__ __align__(256) __nv_bfloat16 g_kb[(size_t)MKEYS * DDIM];  // 2 MB keys, bf16
__device__ __align__(256) float g_kq[MKEYS];                         // |k|^2 (pad = 3e38)
__device__ __align__(256) int   g_cand[(size_t)NPIX * 16];           // 16 candidates / pixel

// ---------------- helpers ----------------
__device__ __forceinline__ uint32_t smem_u32(const void* p) {
    uint32_t a;
    asm("{ .reg .u64 t; cvta.to.shared.u64 t, %1; cvt.u32.u64 %0, t; }" : "=r"(a) : "l"(p));
    return a;
}
#define LDSM_X4(r0, r1, r2, r3, addr) \
    asm volatile("ldmatrix.sync.aligned.m8n8.x4.shared.b16 {%0,%1,%2,%3}, [%4];" \
        : "=r"(r0), "=r"(r1), "=r"(r2), "=r"(r3) : "r"(addr))

__device__ __forceinline__ void mma_bf16(float* d, const uint32_t* a, uint32_t b0, uint32_t b1) {
    asm volatile(
        "mma.sync.aligned.m16n8k16.row.col.f32.bf16.bf16.f32 "
        "{%0,%1,%2,%3}, {%4,%5,%6,%7}, {%8,%9}, {%0,%1,%2,%3};\n"
        : "+f"(d[0]), "+f"(d[1]), "+f"(d[2]), "+f"(d[3])
        : "r"(a[0]), "r"(a[1]), "r"(a[2]), "r"(a[3]), "r"(b0), "r"(b1));
}

// sorted ascending top-2 insert (s[0] best)
__device__ __forceinline__ void ins2(float sc, int idx, float s[2], int id[2]) {
    if (sc < s[1]) {
        if (sc < s[0]) { s[1] = s[0]; id[1] = id[0]; s[0] = sc; id[0] = idx; }
        else           { s[1] = sc;  id[1] = idx; }
    }
}

// =================== kernel 1: key prep ===================
__global__ void prep_keys_k(const float* __restrict__ keys) {
    int j = blockIdx.x;          // 0..MKEYS-1
    int t = threadIdx.x;         // 128 threads
    float s = 0.f;
    if (j < NKEYS) {
        float4 v = ((const float4*)(keys + (size_t)j * DDIM))[t];
        s = v.x*v.x + v.y*v.y + v.z*v.z + v.w*v.w;
        __nv_bfloat162* dst = (__nv_bfloat162*)(g_kb + (size_t)j * DDIM);
        dst[2*t+0] = __floats2bfloat162_rn(v.x, v.y);
        dst[2*t+1] = __floats2bfloat162_rn(v.z, v.w);
    } else {
        // exactly ONE row: float2 = 4 bf16, 128 thr covers 512 halves.
        // (R7-R10 bug: an extra store here overflowed g_kb into g_kq.)
        ((float2*)(g_kb + (size_t)j * DDIM))[t] = make_float2(0.f, 0.f);
    }
    #pragma unroll
    for (int o = 16; o; o >>= 1) s += __shfl_xor_sync(0xffffffffu, s, o);
    __shared__ float ws[4];
    if ((t & 31) == 0) ws[t >> 5] = s;
    __syncthreads();
    if (t == 0) g_kq[j] = (j < NKEYS) ? (ws[0] + ws[1] + ws[2] + ws[3]) : 3.0e38f;
}

// =================== kernel 2: normalize + transpose (bf16 + fp32 out) =====
__global__ void __launch_bounds__(256) normalize_k(const float* __restrict__ query) {
    extern __shared__ float tile[];            // [512][68]
    __shared__ float part[16][16][4];
    __shared__ float rnw[64];

    int bh = blockIdx.x;                       // b*64 + h
    int b = bh >> 6, h = bh & 63;
    const float* base = query + (size_t)b * (512 * 4096) + (size_t)h * 64;
    int t = threadIdx.x;

    float a0 = 0.f, a1 = 0.f, a2 = 0.f, a3 = 0.f;
    #pragma unroll
    for (int i = 0; i < 32; i++) {
        int idx = t + i * 256;
        int c = idx >> 4, w4 = idx & 15;
        float4 v = *(const float4*)(base + (size_t)c * 4096 + w4 * 4);
        *(float4*)(tile + c * 68 + w4 * 4) = v;
        a0 = fmaf(v.x, v.x, a0); a1 = fmaf(v.y, v.y, a1);
        a2 = fmaf(v.z, v.z, a2); a3 = fmaf(v.w, v.w, a3);
    }
    part[t & 15][t >> 4][0] = a0; part[t & 15][t >> 4][1] = a1;
    part[t & 15][t >> 4][2] = a2; part[t & 15][t >> 4][3] = a3;
    __syncthreads();
    if (t < 64) {
        float s = 0.f;
        #pragma unroll
        for (int m = 0; m < 16; m++) s += part[t >> 2][m][t & 3];
        rnw[t] = 1.f / fmaxf(sqrtf(s), 1e-12f);
    }
    __syncthreads();

    int lane = t & 31, warp = t >> 5;
    #pragma unroll
    for (int it = 0; it < 8; it++) {
        int w = warp * 8 + it;
        float rn = rnw[w];
        __nv_bfloat162* dstb = (__nv_bfloat162*)(g_qb + (size_t)(bh * 64 + w) * DDIM);
        float* dstf = g_qf + (size_t)(bh * 64 + w) * DDIM;
        #pragma unroll
        for (int j = 0; j < 8; j++) {
            int c = j * 64 + lane * 2;
            float x = tile[c * 68 + w] * rn;
            float y = tile[(c + 1) * 68 + w] * rn;
            dstb[j * 32 + lane] = __floats2bfloat162_rn(x, y);
            *(float2*)(dstf + c) = make_float2(x, y);
        }
    }
}

// =================== kernel 3: HMMA GEMM + per-thread top-2 ===============
// 256 CTAs x 256 thr (8 warps, 4x2 warp grid; warp tile 32M x 64N).
// Identical to R12 (passing) except fragment loads: ldmatrix.x4 instead of
// 24 scalar LDS per warp k-step (A: 2 LDSM, B: 4 LDSM). Strides 1040B/144B
// give per-row bank offset 4 -> 8 rows on distinct bank quads, conflict-free.
#define SM_A   0
#define SM_B   133120          // 128*520*2
#define SM_KQ  (133120 + 36864)
#define SMEM_G (SM_KQ + 8192)

__global__ void __launch_bounds__(256, 1) gemm_hmma_k() {
    extern __shared__ unsigned char sm[];
    uint32_t sb = smem_u32(sm);
    float* kqs = (float*)(sm + SM_KQ);

    int t = threadIdx.x, lane = t & 31, warp = t >> 5;
    int wm = warp >> 1, wn = warp & 1;
    int p0 = blockIdx.x * 128;

    // ---- A fill: g_qb[p0..p0+127][0..511] -> rows of 520 halves (65 uint4) ----
    {
        const uint4* src = (const uint4*)(g_qb + (size_t)p0 * DDIM);
        uint4* dst = (uint4*)sm;
        #pragma unroll
        for (int i = 0; i < 32; i++) {
            int idx = t + i * 256;
            int r = idx >> 6, c = idx & 63;
            dst[r * 65 + c] = src[r * 64 + c];
        }
    }
    // ---- kq fill ----
    #pragma unroll
    for (int i = 0; i < 8; i++) kqs[t + i * 256] = g_kq[t + i * 256];

    // ---- per-thread B transfer coordinates (fixed across chunks) ----
    const uint4* kb4 = (const uint4*)g_kb;
    int br_[4], bc_[4];
    #pragma unroll
    for (int i = 0; i < 4; i++) {
        int idx = t + i * 256;
        br_[i] = idx >> 3;            // key row within 128-chunk
        bc_[i] = idx & 7;             // uint4 col within 8 (64 halves)
    }
    // ---- prefetch chunk g=0 (tile 0, kc 0) into registers ----
    uint4 breg[4];
    #pragma unroll
    for (int i = 0; i < 4; i++)
        breg[i] = kb4[(size_t)br_[i] * 64 + bc_[i]];

    // ---- ldmatrix per-lane base addresses ----
    // lanes 0-7: rows 0-7 (k lo) | 8-15: rows 8-15 (k lo) |
    // 16-23: rows 0-7 (k hi, +16B) | 24-31: rows 8-15 (k hi)
    int lrow8 = ((lane >> 3) & 1) * 8 + (lane & 7);
    int koff  = ((lane >> 4) & 1) * 16;               // bytes
    uint32_t baseA[2];
    #pragma unroll
    for (int mt = 0; mt < 2; mt++)
        baseA[mt] = sb + SM_A + (uint32_t)((wm * 32 + mt * 16 + lrow8) * 1040 + koff);
    uint32_t baseB[4];
    #pragma unroll
    for (int p = 0; p < 4; p++)
        baseB[p] = (uint32_t)((wn * 64 + p * 16 + lrow8) * 144 + koff);

    int colbase = wn * 64 + (lane & 3) * 2;

    // ---- per-thread top-2 state: 4 row-slots ----
    float t2s[4][2]; int t2i[4][2];
    #pragma unroll
    for (int s = 0; s < 4; s++) {
        t2s[s][0] = 1e30f; t2s[s][1] = 1e30f;
        t2i[s][0] = 0;     t2i[s][1] = 0;
    }

    float acc[2][8][4];

    #pragma unroll 1
    for (int g = 0; g < 128; g++) {            // g = tile*8 + kc  (16 tiles x 8 K-chunks)
        int tile = g >> 3, kc = g & 7;
        int buf = g & 1;

        // STS prefetched chunk g into buf (single-barrier safe: other
        // buffer's last reads were iter g-2, separated by barrier at g-1)
        {
            unsigned char* bb = sm + SM_B + buf * 18432;
            #pragma unroll
            for (int i = 0; i < 4; i++)
                *(uint4*)(bb + br_[i] * 144 + bc_[i] * 16) = breg[i];
        }
        // LDG chunk g+1 into registers (hidden under this chunk's MMA)
        if (g + 1 < 128) {
            int g1 = g + 1;
            int t1 = g1 >> 3, k1 = g1 & 7;
            #pragma unroll
            for (int i = 0; i < 4; i++)
                breg[i] = kb4[(size_t)(t1 * 128 + br_[i]) * 64 + k1 * 8 + bc_[i]];
        }
        __syncthreads();                       // B[g] visible CTA-wide (covers A on g=0)

        if (kc == 0) {
            #pragma unroll
            for (int mt = 0; mt < 2; mt++)
                #pragma unroll
                for (int nt = 0; nt < 8; nt++)
                    #pragma unroll
                    for (int k = 0; k < 4; k++) acc[mt][nt][k] = 0.f;
        }

        uint32_t bbase = sb + SM_B + (uint32_t)(buf * 18432);
        #pragma unroll
        for (int ks = 0; ks < 4; ks++) {
            uint32_t a[2][4];
            #pragma unroll
            for (int mt = 0; mt < 2; mt++)
                LDSM_X4(a[mt][0], a[mt][1], a[mt][2], a[mt][3],
                        baseA[mt] + (uint32_t)(kc * 128 + ks * 32));
            uint32_t bb[4][4];
            #pragma unroll
            for (int p = 0; p < 4; p++)
                LDSM_X4(bb[p][0], bb[p][1], bb[p][2], bb[p][3],
                        bbase + baseB[p] + (uint32_t)(ks * 32));
            #pragma unroll
            for (int mt = 0; mt < 2; mt++)
                #pragma unroll
                for (int nt = 0; nt < 8; nt++)
                    mma_bf16(acc[mt][nt], a[mt],
                             bb[nt >> 1][nt & 1], bb[nt >> 1][2 + (nt & 1)]);
        }

        if (kc == 7) {                         // fold tile into per-thread top-2
            int kb = tile * 128 + colbase;
            #pragma unroll
            for (int mt = 0; mt < 2; mt++)
                #pragma unroll
                for (int nt = 0; nt < 8; nt++) {
                    int key = kb + nt * 8;
                    float q0 = kqs[key], q1 = kqs[key + 1];
                    ins2(q0 - 2.f * acc[mt][nt][0], key,     t2s[mt*2],   t2i[mt*2]);
                    ins2(q1 - 2.f * acc[mt][nt][1], key + 1, t2s[mt*2],   t2i[mt*2]);
                    ins2(q0 - 2.f * acc[mt][nt][2], key,     t2s[mt*2+1], t2i[mt*2+1]);
                    ins2(q1 - 2.f * acc[mt][nt][3], key + 1, t2s[mt*2+1], t2i[mt*2+1]);
                }
        }
    }

    // ---- writeout: every thread writes ITS OWN candidate slots ----
    #pragma unroll
    for (int s = 0; s < 4; s++) {
        int row  = wm * 32 + (s >> 1) * 16 + (s & 1) * 8 + (lane >> 2);
        int slot = (wn * 4 + (lane & 3)) * 2;
        *(int2*)(g_cand + (size_t)(p0 + row) * 16 + slot) =
            make_int2(t2i[s][0], t2i[s][1]);
    }
}

// =================== kernel 4: exact fp32 rescore (16 cands) + L4 =========
__global__ void __launch_bounds__(256) finalize16_k(const float* __restrict__ keys,
                                                    float* __restrict__ out) {
    int warp = threadIdx.x >> 5, lane = threadIdx.x & 31;
    int p = blockIdx.x * 8 + warp;
    const float* q = g_qf + (size_t)p * DDIM;
    float qr[16];
    #pragma unroll
    for (int j = 0; j < 16; j++) qr[j] = q[j * 32 + lane];

    float best = 3.4e38f; int bidx = 0x7fffffff;
    #pragma unroll 1
    for (int c = 0; c < 16; c++) {
        int k = g_cand[(size_t)p * 16 + c];
        const float* kr = keys + (size_t)k * DDIM;
        float d = 0.f;
        #pragma unroll
        for (int j = 0; j < 16; j++) d = fmaf(qr[j], kr[j * 32 + lane], d);
        #pragma unroll
        for (int o = 16; o; o >>= 1) d += __shfl_xor_sync(0xffffffffu, d, o);
        float sc = g_kq[k] - 2.f * d;
        if (sc < best || (sc == best && k < bidx)) { best = sc; bidx = k; }
    }
    const float* kr = keys + (size_t)bidx * DDIM;
    float hs = 0.f;
    #pragma unroll
    for (int j = 0; j < 16; j++) {
        float diff = qr[j] - kr[j * 32 + lane];
        float d2 = diff * diff;
        hs = fmaf(d2, d2, hs);
    }
    #pragma unroll
    for (int o = 16; o; o >>= 1) hs += __shfl_xor_sync(0xffffffffu, hs, o);
    if (lane == 0) out[p] = hs;
}

// =================== launch ===================
extern "C" void kernel_launch(void* const* d_in, const int* in_sizes, int n_in,
                              void* d_out, int out_size) {
    const float* query = (const float*)d_in[0];
    const float* keys  = (const float*)d_in[1];
    if (n_in >= 2 && in_sizes[0] == NKEYS * DDIM) {   // defensive input-order swap
        query = (const float*)d_in[1];
        keys  = (const float*)d_in[0];
    }
    float* out = (float*)d_out;

    cudaFuncSetAttribute(normalize_k,  cudaFuncAttributeMaxDynamicSharedMemorySize, 512 * 68 * 4);
    cudaFuncSetAttribute(gemm_hmma_k,  cudaFuncAttributeMaxDynamicSharedMemorySize, SMEM_G);

    prep_keys_k<<<MKEYS, 128>>>(keys);
    normalize_k<<<512, 256, 512 * 68 * 4>>>(query);
    gemm_hmma_k<<<256, 256, SMEM_G>>>();
    finalize16_k<<<NPIX / 8, 256>>>(keys, out);
}